// round 1
// baseline (speedup 1.0000x reference)
#include <cuda_runtime.h>
#include <cstdint>

// Max-unpool 2x2 (kernel=stride=2, non-overlapping).
// x:     [N, C, H, W]   fp32
// where: [N, C, H, W]   int32 in {0,1,2,3} (position within 2x2 window, row-major)
// out:   [N, C, 2H, 2W] fp32
//
// Each thread handles 4 consecutive input pixels along W:
//   reads  float4 x + int4 where (32 B)
//   writes 8 floats in output row 2h and 8 floats in row 2h+1 (4x STG.128, 64 B)
// Zeros synthesized in-register; no memset pass.

static constexpr int N = 32, C = 64, H = 64, W = 64;
static constexpr int W4 = W / 4;          // float4 chunks per input row
static constexpr int OW = 2 * W;          // output width = 128
static constexpr int ROWS = N * C * H;    // input rows total

__global__ __launch_bounds__(256)
void unpool2x2_kernel(const float4* __restrict__ x4,
                      const int4* __restrict__ w4,
                      float* __restrict__ out)
{
    int idx = blockIdx.x * blockDim.x + threadIdx.x;     // 0 .. ROWS*W4-1
    if (idx >= ROWS * W4) return;

    int qw  = idx % W4;          // which float4 chunk within the row
    int row = idx / W4;          // combined (n,c,h)
    int h   = row % H;
    int nc  = row / H;

    float4 xv = x4[idx];
    int4   wv = w4[idx];

    // Build the 8-wide top row and bottom row for these 4 pixels.
    // pixel j -> output cols 2j, 2j+1 within the 8-span.
    float4 top0, top1;   // top row: cols [0..3], [4..7] of span
    {
        // pixels 0,1 -> top0 ; pixels 2,3 -> top1
        top0.x = (wv.x == 0) ? xv.x : 0.f;
        top0.y = (wv.x == 1) ? xv.x : 0.f;
        top0.z = (wv.y == 0) ? xv.y : 0.f;
        top0.w = (wv.y == 1) ? xv.y : 0.f;
        top1.x = (wv.z == 0) ? xv.z : 0.f;
        top1.y = (wv.z == 1) ? xv.z : 0.f;
        top1.z = (wv.w == 0) ? xv.w : 0.f;
        top1.w = (wv.w == 1) ? xv.w : 0.f;
    }
    float4 bot0, bot1;   // bottom row
    {
        bot0.x = (wv.x == 2) ? xv.x : 0.f;
        bot0.y = (wv.x == 3) ? xv.x : 0.f;
        bot0.z = (wv.y == 2) ? xv.y : 0.f;
        bot0.w = (wv.y == 3) ? xv.y : 0.f;
        bot1.x = (wv.z == 2) ? xv.z : 0.f;
        bot1.y = (wv.z == 3) ? xv.z : 0.f;
        bot1.z = (wv.w == 2) ? xv.w : 0.f;
        bot1.w = (wv.w == 3) ? xv.w : 0.f;
    }

    // Output base: image nc, row 2h, col qw*8
    size_t obase = (size_t)nc * (2 * H * OW) + (size_t)(2 * h) * OW + (size_t)qw * 8;
    float4* o_top = reinterpret_cast<float4*>(out + obase);
    float4* o_bot = reinterpret_cast<float4*>(out + obase + OW);

    o_top[0] = top0;
    o_top[1] = top1;
    o_bot[0] = bot0;
    o_bot[1] = bot1;
}

extern "C" void kernel_launch(void* const* d_in, const int* in_sizes, int n_in,
                              void* d_out, int out_size)
{
    const float4* x4 = (const float4*)d_in[0];
    const int4*   w4 = (const int4*)d_in[1];
    float* out = (float*)d_out;

    int total = ROWS * W4;           // 2,097,152 threads
    int threads = 256;
    int blocks = (total + threads - 1) / threads;
    unpool2x2_kernel<<<blocks, threads>>>(x4, w4, out);
}

// round 2
// speedup vs baseline: 1.1159x; 1.1159x over previous
#include <cuda_runtime.h>
#include <cstdint>

// Max-unpool 2x2 (kernel=stride=2, non-overlapping).
// x:     [N, C, H, W]   fp32
// where: [N, C, H, W]   int32 in {0..3} (row-major position within 2x2 window)
// out:   [N, C, 2H, 2W] fp32
//
// R2: one thread = 2 consecutive input pixels -> one float4 per output row.
// Warp store addresses stride by exactly 16B -> every STG.128 is a dense
// 512B warp transaction (full 32B sectors), halving L1 store wavefronts vs R1.

static constexpr int N = 32, C = 64, H = 64, W = 64;
static constexpr int W2 = W / 2;          // 2-pixel chunks per input row = 32
static constexpr int OW = 2 * W;          // output width = 128
static constexpr int ROWS = N * C * H;    // input rows total
static constexpr int TOTAL = ROWS * W2;   // threads

__global__ __launch_bounds__(256)
void unpool2x2_kernel(const float2* __restrict__ x2,
                      const int2* __restrict__ w2,
                      float* __restrict__ out)
{
    int idx = blockIdx.x * blockDim.x + threadIdx.x;   // 0 .. TOTAL-1
    if (idx >= TOTAL) return;

    int qw  = idx & (W2 - 1);      // chunk within row (W2=32, power of 2)
    int row = idx >> 5;            // combined (n,c,h)
    int h   = row & (H - 1);
    int nc  = row >> 6;

    float2 xv = x2[idx];
    int2   wv = w2[idx];

    // pixel 0 -> output cols 0,1 of the 4-span; pixel 1 -> cols 2,3
    float4 top, bot;
    top.x = (wv.x == 0) ? xv.x : 0.f;
    top.y = (wv.x == 1) ? xv.x : 0.f;
    top.z = (wv.y == 0) ? xv.y : 0.f;
    top.w = (wv.y == 1) ? xv.y : 0.f;

    bot.x = (wv.x == 2) ? xv.x : 0.f;
    bot.y = (wv.x == 3) ? xv.x : 0.f;
    bot.z = (wv.y == 2) ? xv.y : 0.f;
    bot.w = (wv.y == 3) ? xv.y : 0.f;

    // Output base: image nc, row 2h, col qw*4
    size_t obase = (size_t)nc * (2 * H * OW) + (size_t)(2 * h) * OW + (size_t)qw * 4;
    *reinterpret_cast<float4*>(out + obase)      = top;
    *reinterpret_cast<float4*>(out + obase + OW) = bot;
}

extern "C" void kernel_launch(void* const* d_in, const int* in_sizes, int n_in,
                              void* d_out, int out_size)
{
    const float2* x2 = (const float2*)d_in[0];
    const int2*   w2 = (const int2*)d_in[1];
    float* out = (float*)d_out;

    int threads = 256;
    int blocks = (TOTAL + threads - 1) / threads;   // 16384
    unpool2x2_kernel<<<blocks, threads>>>(x2, w2, out);
}